// round 9
// baseline (speedup 1.0000x reference)
#include <cuda_runtime.h>
#include <math.h>
#include <stdint.h>

// CRF loss: L=512 seq, B=512 batch, T=128 tags.
#define LL 512
#define BB 512
#define TT 128
#define NBC 2             // batches per CTA
#define NCTA (BB/NBC)     // 256 CTAs -> 2 CTAs/SM
#define NTHREADS 256
#define PHALF 68          // padded j-half stride (floats): halves on disjoint bank groups
#define PB (2*PHALF)      // padded per-batch alpha row = 136 floats
#define LN2F 0.6931471805599453f

__device__ float g_logZ[BB];
__device__ float g_num[BB];

union F4U { float4 v; struct { unsigned long long p01, p23; } u; };

__device__ __forceinline__ unsigned long long ffma2(unsigned long long a,
                                                    unsigned long long b,
                                                    unsigned long long c) {
    unsigned long long d;
    asm("fma.rn.f32x2 %0, %1, %2, %3;" : "=l"(d) : "l"(a), "l"(b), "l"(c));
    return d;
}
__device__ __forceinline__ unsigned long long packf2(float lo, float hi) {
    unsigned long long r;
    asm("mov.b64 %0, {%1,%2};" : "=l"(r) : "f"(lo), "f"(hi));
    return r;
}
__device__ __forceinline__ float2 unpackf2(unsigned long long v) {
    float2 f;
    asm("mov.b64 {%0,%1}, %2;" : "=f"(f.x), "=f"(f.y) : "l"(v));
    return f;
}

// Org: 8 warps, 2 batches/CTA. Lane: jq = lane>>4 (j-half AND assigned batch),
// kidx = lane&15, kk = w*16+kidx (assigned tag). Tile: 64j x 1k x 2b = 64 FFMA2.
// E: 64 floats = 32 u64 regs. Reduce: ONE shfl level (^16). One bar per step.
__global__ __launch_bounds__(NTHREADS, 2)
void crf_forward(const float* __restrict__ emissions,
                 const int* __restrict__ mask,
                 const float* __restrict__ start_t,
                 const float* __restrict__ end_t,
                 const float* __restrict__ trans)
{
    __shared__ __align__(16) float sPA[NBC * PB];   // ping
    __shared__ __align__(16) float sPB[NBC * PB];   // pong
    __shared__ __align__(16) float sZf[NBC][TT];
    __shared__ int sEa[NBC];

    const int tid  = threadIdx.x;
    const int w    = tid >> 5;
    const int lane = tid & 31;
    const int jq   = lane >> 4;          // j-half; also assigned local batch
    const int kidx = lane & 15;
    const int kk   = w * 16 + kidx;      // assigned tag
    const int gb   = blockIdx.x * NBC + jq;
    const int ka   = jq * PB + ((kk >> 6) * PHALF + (kk & 63));  // addr of (b=jq, kk)
    const int jb   = jq * PHALF;         // lane's j-half offset within a batch row
    const int eb   = jq * PB;            // lane's batch row base (for est)

    // ---- E column kk over lane's j-half: 32 u64 regs ----
    unsigned long long eR[32];
    #pragma unroll
    for (int t = 0; t < 32; ++t) {
        int j = jq * 64 + 2 * t;
        eR[t] = packf2(__expf(trans[j * TT + kk]),
                       __expf(trans[(j + 1) * TT + kk]));
    }

    // ---- init: p~0[b=jq][kk] ----
    sPA[ka] = __expf(start_t[kk] + emissions[(size_t)gb * TT + kk]);
    __syncthreads();

    int e_acc = 0;

    // one-step-ahead prefetch of this lane's emission/mask
    float em = emissions[((size_t)1 * BB + gb) * TT + kk];
    int   m  = mask[1 * BB + gb];

    // ---- one step: Pin -> Pout ----
    #define STEP(Pin, Pout, I)                                                  \
    {                                                                            \
        const float4 ev = *(const float4*)&(Pin)[eb];                            \
        float s  = (ev.x + ev.y) + (ev.z + ev.w);                                \
        int   es = ((__float_as_int(s) >> 23) & 255) - 126;                      \
        float factor = __expf(em) * __int_as_float((127 - es) << 23);            \
        float oldp = (Pin)[ka];                                                  \
        int inx = ((I) + 1 < LL) ? (I) + 1 : LL - 1;                             \
        float nem = emissions[((size_t)inx * BB + gb) * TT + kk];                \
        int   nm  = mask[inx * BB + gb];                                         \
        unsigned long long a0 = 0, a1 = 0;                                       \
        _Pragma("unroll")                                                        \
        for (int t = 0; t < 16; ++t) {                                           \
            F4U p0; p0.v = *(const float4*)((Pin) + jb + 4 * t);                 \
            F4U p1; p1.v = *(const float4*)((Pin) + PB + jb + 4 * t);            \
            a0 = ffma2(p0.u.p01, eR[2 * t],     a0);                             \
            a1 = ffma2(p1.u.p01, eR[2 * t],     a1);                             \
            a0 = ffma2(p0.u.p23, eR[2 * t + 1], a0);                             \
            a1 = ffma2(p1.u.p23, eR[2 * t + 1], a1);                             \
        }                                                                        \
        float2 h0 = unpackf2(a0), h1 = unpackf2(a1);                             \
        float q0 = h0.x + h0.y;                                                  \
        float q1 = h1.x + h1.y;                                                  \
        q0 += __shfl_xor_sync(0xffffffffu, q0, 16);                              \
        q1 += __shfl_xor_sync(0xffffffffu, q1, 16);                              \
        float mine = jq ? q1 : q0;                                               \
        float outv;                                                              \
        if (m) { outv = mine * factor; e_acc += es; }                            \
        else   { outv = oldp; }                                                  \
        (Pout)[ka] = outv;                                                       \
        em = nem; m = nm;                                                        \
        __syncthreads();                                                         \
    }

    // 511 steps: 255 unrolled pairs (A->B->A) + final single (A->B)
    for (int i = 1; i <= 509; i += 2) {
        STEP(sPA, sPB, i);
        STEP(sPB, sPA, i + 1);
    }
    STEP(sPA, sPB, 511);
    #undef STEP

    // ---- finalize: logZ = e_acc*ln2 + log( sum_k p~[k]*exp(end[k]) ) ----
    sZf[jq][kk] = sPB[ka] * __expf(end_t[kk]);
    if (w == 0 && kidx == 0) sEa[jq] = e_acc;
    __syncthreads();
    if (w == 0) {
        #pragma unroll
        for (int b = 0; b < NBC; ++b) {
            float v = sZf[b][lane] + sZf[b][lane + 32]
                    + sZf[b][lane + 64] + sZf[b][lane + 96];
            v += __shfl_xor_sync(0xffffffffu, v, 1);
            v += __shfl_xor_sync(0xffffffffu, v, 2);
            v += __shfl_xor_sync(0xffffffffu, v, 4);
            v += __shfl_xor_sync(0xffffffffu, v, 8);
            v += __shfl_xor_sync(0xffffffffu, v, 16);
            if (lane == 0)
                g_logZ[blockIdx.x * NBC + b] = (float)sEa[b] * LN2F + logf(v);
        }
    }
}

// Numerator: one block per batch.
__global__ void crf_num(const float* __restrict__ emissions,
                        const int*   __restrict__ tags,
                        const int*   __restrict__ mask,
                        const float* __restrict__ start_t,
                        const float* __restrict__ end_t,
                        const float* __restrict__ trans)
{
    const int b   = blockIdx.x;
    const int tid = threadIdx.x;
    __shared__ float rf[256];
    __shared__ int   ri[256];

    float loc = 0.f;
    int   cnt = 0;
    for (int i = tid; i < LL; i += 256) {
        int tag = tags[i * BB + b];
        int m   = mask[i * BB + b];
        if (m) {
            loc += emissions[((size_t)i * BB + b) * TT + tag];
            cnt++;
            if (i > 0) loc += trans[tags[(i - 1) * BB + b] * TT + tag];
        }
        if (i == 0) loc += start_t[tag];
    }
    rf[tid] = loc; ri[tid] = cnt;
    __syncthreads();
    #pragma unroll
    for (int s = 128; s > 0; s >>= 1) {
        if (tid < s) { rf[tid] += rf[tid + s]; ri[tid] += ri[tid + s]; }
        __syncthreads();
    }
    if (tid == 0) {
        int ends = ri[0] - 1;
        if (ends < 0) ends = 0;
        g_num[b] = rf[0] + end_t[tags[ends * BB + b]];
    }
}

__global__ void crf_final(float* __restrict__ out)
{
    __shared__ float r[512];
    const int tid = threadIdx.x;
    r[tid] = g_logZ[tid] - g_num[tid];
    __syncthreads();
    #pragma unroll
    for (int s = 256; s > 0; s >>= 1) {
        if (tid < s) r[tid] += r[tid + s];
        __syncthreads();
    }
    if (tid == 0) out[0] = r[0] * (1.0f / (float)BB);
}

extern "C" void kernel_launch(void* const* d_in, const int* in_sizes, int n_in,
                              void* d_out, int out_size)
{
    const float* emissions = (const float*)d_in[0];
    const int*   tags      = (const int*)d_in[1];
    const int*   mask      = (const int*)d_in[2];
    const float* start_t   = (const float*)d_in[3];
    const float* end_t     = (const float*)d_in[4];
    const float* trans     = (const float*)d_in[5];
    float*       out       = (float*)d_out;

    crf_forward<<<NCTA, NTHREADS>>>(emissions, mask, start_t, end_t, trans);
    crf_num<<<BB, 256>>>(emissions, tags, mask, start_t, end_t, trans);
    crf_final<<<1, BB>>>(out);
}

// round 10
// speedup vs baseline: 1.0060x; 1.0060x over previous
#include <cuda_runtime.h>
#include <math.h>
#include <stdint.h>

// CRF loss: L=512 seq, B=512 batch, T=128 tags.
#define LL 512
#define BB 512
#define TT 128
#define NBC 2             // batches per CTA
#define NCTA (BB/NBC)     // 256 CTAs -> 2 CTAs/SM
#define NTHREADS 256
#define PHALF 68          // padded j-half stride (floats)
#define PB (2*PHALF)      // padded per-batch alpha row = 136 floats
#define LN2F 0.6931471805599453f

__device__ float g_logZ[BB];
__device__ float g_num[BB];

union F4U { float4 v; struct { unsigned long long p01, p23; } u; };

__device__ __forceinline__ unsigned long long ffma2(unsigned long long a,
                                                    unsigned long long b,
                                                    unsigned long long c) {
    unsigned long long d;
    asm("fma.rn.f32x2 %0, %1, %2, %3;" : "=l"(d) : "l"(a), "l"(b), "l"(c));
    return d;
}
__device__ __forceinline__ unsigned long long packf2(float lo, float hi) {
    unsigned long long r;
    asm("mov.b64 %0, {%1,%2};" : "=l"(r) : "f"(lo), "f"(hi));
    return r;
}
__device__ __forceinline__ float2 unpackf2(unsigned long long v) {
    float2 f;
    asm("mov.b64 {%0,%1}, %2;" : "=f"(f.x), "=f"(f.y) : "l"(v));
    return f;
}

// Org: 8 warps, 2 batches/CTA. Lane: jq = lane>>4 (j-half AND assigned batch),
// kk = w*16 + (lane&15) (assigned tag). Tile: 64j x 1k x 2b = 64 FFMA2/step.
// Tail: ONE butterfly shfl (^16). Anti-phase skew decorrelates co-resident CTAs.
__global__ __launch_bounds__(NTHREADS, 2)
void crf_forward(const float* __restrict__ emissions,
                 const int* __restrict__ mask,
                 const float* __restrict__ start_t,
                 const float* __restrict__ end_t,
                 const float* __restrict__ trans)
{
    __shared__ __align__(16) float sPA[NBC * PB];   // ping
    __shared__ __align__(16) float sPB[NBC * PB];   // pong
    __shared__ __align__(16) float sZf[NBC][TT];
    __shared__ int sEa[NBC];

    const int tid  = threadIdx.x;
    const int w    = tid >> 5;
    const int lane = tid & 31;
    const int jq   = lane >> 4;          // j-half; also assigned local batch
    const int kidx = lane & 15;
    const int kk   = w * 16 + kidx;      // assigned tag
    const int gb   = blockIdx.x * NBC + jq;
    const int ka   = jq * PB + ((kk >> 6) * PHALF + (kk & 63));  // addr of (b=jq, kk)
    const int jb   = jq * PHALF;         // lane's j-half offset within a batch row
    const int eb   = jq * PB;            // lane's batch row base (for scale est)

    // ---- E column kk over lane's j-half: 32 u64 regs ----
    unsigned long long eR[32];
    #pragma unroll
    for (int t = 0; t < 32; ++t) {
        int j = jq * 64 + 2 * t;
        eR[t] = packf2(__expf(trans[j * TT + kk]),
                       __expf(trans[(j + 1) * TT + kk]));
    }

    // ---- init: p~0[b=jq][kk] ----
    sPA[ka] = __expf(start_t[kk] + emissions[(size_t)gb * TT + kk]);
    __syncthreads();

    // ---- anti-phase skew: delay second-wave CTAs (~320 cyc dependent chain) ----
    if (blockIdx.x >= 148) {
        float d = 1.0f + (float)(tid & 1) * 1e-7f;
        #pragma unroll
        for (int t = 0; t < 80; ++t)
            d = fmaf(d, 1.0000001f, 1e-7f);
        if (__float_as_int(d) == 0) sEa[0] = 1;   // never true; keeps chain alive
    }

    int e_acc = 0;

    // one-step-ahead prefetch of this lane's emission/mask
    float em = emissions[((size_t)1 * BB + gb) * TT + kk];
    int   m  = mask[1 * BB + gb];

    // ---- one step: Pin -> Pout ----
    #define STEP(Pin, Pout, I)                                                  \
    {                                                                            \
        const float4 ev = *(const float4*)&(Pin)[eb];                            \
        float s  = (ev.x + ev.y) + (ev.z + ev.w);                                \
        int   es = ((__float_as_int(s) >> 23) & 255) - 126;                      \
        float factor = __expf(em) * __int_as_float((127 - es) << 23);            \
        float oldp = (Pin)[ka];                                                  \
        int inx = ((I) + 1 < LL) ? (I) + 1 : LL - 1;                             \
        float nem = emissions[((size_t)inx * BB + gb) * TT + kk];                \
        int   nm  = mask[inx * BB + gb];                                         \
        unsigned long long a0 = 0, a1 = 0;                                       \
        _Pragma("unroll")                                                        \
        for (int t = 0; t < 16; ++t) {                                           \
            F4U p0; p0.v = *(const float4*)((Pin) + jb + 4 * t);                 \
            F4U p1; p1.v = *(const float4*)((Pin) + PB + jb + 4 * t);            \
            a0 = ffma2(p0.u.p01, eR[2 * t],     a0);                             \
            a1 = ffma2(p1.u.p01, eR[2 * t],     a1);                             \
            a0 = ffma2(p0.u.p23, eR[2 * t + 1], a0);                             \
            a1 = ffma2(p1.u.p23, eR[2 * t + 1], a1);                             \
        }                                                                        \
        float2 h0 = unpackf2(a0), h1 = unpackf2(a1);                             \
        float q0 = h0.x + h0.y;   /* batch 0 partial (lane's j-half) */          \
        float q1 = h1.x + h1.y;   /* batch 1 partial */                          \
        float send = jq ? q0 : q1;            /* give partner ITS batch */       \
        float recv = __shfl_xor_sync(0xffffffffu, send, 16);                     \
        float mine = (jq ? q1 : q0) + recv;                                      \
        float outv;                                                              \
        if (m) { outv = mine * factor; e_acc += es; }                            \
        else   { outv = oldp; }                                                  \
        (Pout)[ka] = outv;                                                       \
        em = nem; m = nm;                                                        \
        __syncthreads();                                                         \
    }

    // 511 steps: 255 unrolled pairs (A->B->A) + final single (A->B)
    for (int i = 1; i <= 509; i += 2) {
        STEP(sPA, sPB, i);
        STEP(sPB, sPA, i + 1);
    }
    STEP(sPA, sPB, 511);
    #undef STEP

    // ---- finalize: logZ = e_acc*ln2 + log( sum_k p~[k]*exp(end[k]) ) ----
    sZf[jq][kk] = sPB[ka] * __expf(end_t[kk]);
    if (w == 0 && kidx == 0) sEa[jq] = e_acc;
    __syncthreads();
    if (w == 0) {
        #pragma unroll
        for (int b = 0; b < NBC; ++b) {
            float v = sZf[b][lane] + sZf[b][lane + 32]
                    + sZf[b][lane + 64] + sZf[b][lane + 96];
            v += __shfl_xor_sync(0xffffffffu, v, 1);
            v += __shfl_xor_sync(0xffffffffu, v, 2);
            v += __shfl_xor_sync(0xffffffffu, v, 4);
            v += __shfl_xor_sync(0xffffffffu, v, 8);
            v += __shfl_xor_sync(0xffffffffu, v, 16);
            if (lane == 0)
                g_logZ[blockIdx.x * NBC + b] = (float)sEa[b] * LN2F + logf(v);
        }
    }
}

// Numerator: one block per batch.
__global__ void crf_num(const float* __restrict__ emissions,
                        const int*   __restrict__ tags,
                        const int*   __restrict__ mask,
                        const float* __restrict__ start_t,
                        const float* __restrict__ end_t,
                        const float* __restrict__ trans)
{
    const int b   = blockIdx.x;
    const int tid = threadIdx.x;
    __shared__ float rf[256];
    __shared__ int   ri[256];

    float loc = 0.f;
    int   cnt = 0;
    for (int i = tid; i < LL; i += 256) {
        int tag = tags[i * BB + b];
        int m   = mask[i * BB + b];
        if (m) {
            loc += emissions[((size_t)i * BB + b) * TT + tag];
            cnt++;
            if (i > 0) loc += trans[tags[(i - 1) * BB + b] * TT + tag];
        }
        if (i == 0) loc += start_t[tag];
    }
    rf[tid] = loc; ri[tid] = cnt;
    __syncthreads();
    #pragma unroll
    for (int s = 128; s > 0; s >>= 1) {
        if (tid < s) { rf[tid] += rf[tid + s]; ri[tid] += ri[tid + s]; }
        __syncthreads();
    }
    if (tid == 0) {
        int ends = ri[0] - 1;
        if (ends < 0) ends = 0;
        g_num[b] = rf[0] + end_t[tags[ends * BB + b]];
    }
}

__global__ void crf_final(float* __restrict__ out)
{
    __shared__ float r[512];
    const int tid = threadIdx.x;
    r[tid] = g_logZ[tid] - g_num[tid];
    __syncthreads();
    #pragma unroll
    for (int s = 256; s > 0; s >>= 1) {
        if (tid < s) r[tid] += r[tid + s];
        __syncthreads();
    }
    if (tid == 0) out[0] = r[0] * (1.0f / (float)BB);
}

extern "C" void kernel_launch(void* const* d_in, const int* in_sizes, int n_in,
                              void* d_out, int out_size)
{
    const float* emissions = (const float*)d_in[0];
    const int*   tags      = (const int*)d_in[1];
    const int*   mask      = (const int*)d_in[2];
    const float* start_t   = (const float*)d_in[3];
    const float* end_t     = (const float*)d_in[4];
    const float* trans     = (const float*)d_in[5];
    float*       out       = (float*)d_out;

    crf_forward<<<NCTA, NTHREADS>>>(emissions, mask, start_t, end_t, trans);
    crf_num<<<BB, 256>>>(emissions, tags, mask, start_t, end_t, trans);
    crf_final<<<1, BB>>>(out);
}